// round 4
// baseline (speedup 1.0000x reference)
#include <cuda_runtime.h>
#include <cuda_bf16.h>
#include <math.h>
#include <stdint.h>

#define T_TOK 2048
#define H_DIM 1024
#define I_DIM 1024
#define S_LEN 1024
#define B_SZ  2
#define NH    16
#define NKV   4
#define HD    64
#define NE    8
#define TCAP  2048

// ---------------- scratch (no allocs allowed; __device__ globals) ----------------
__device__ float g_x1[T_TOK * H_DIM];        // rmsnorm1 out, later reused as sharedY
__device__ float g_q[T_TOK * NH * HD];
__device__ float g_k[T_TOK * NKV * HD];
__device__ float g_v[T_TOK * NKV * HD];
__device__ float g_attn[T_TOK * NH * HD];
__device__ float g_resid[T_TOK * H_DIM];
__device__ float g_x2[T_TOK * H_DIM];
__device__ float g_moe[T_TOK * H_DIM];
__device__ float g_G[NE * TCAP * I_DIM];     // gate out / silu*up in-place; reused for shared
__device__ float g_U[NE * TCAP * I_DIM];
__device__ float g_probs[T_TOK * NE];
__device__ int   g_cnt[NE];
__device__ int   g_asg_tok[NE * TCAP];
__device__ float g_asg_w[NE * TCAP];
__device__ float g_sgate[T_TOK];

// ---------------- zero (must be in graph: replays need fresh state) ----------------
__global__ void zero_kernel()
{
    int i = blockIdx.x * blockDim.x + threadIdx.x;
    if (i < T_TOK * H_DIM) g_moe[i] = 0.f;
    if (i < NE) g_cnt[i] = 0;
}

// ---------------- RMSNorm: one block / token, 256 thr * float4 ----------------
__global__ void rmsnorm_kernel(const float* __restrict__ x, const float* __restrict__ w,
                               float* __restrict__ y)
{
    __shared__ float red[8];
    __shared__ float s_inv;
    int t = blockIdx.x;
    int tid = threadIdx.x;
    const float4* xp = (const float4*)(x + (size_t)t * H_DIM);
    float4 v = xp[tid];
    float ss = v.x * v.x + v.y * v.y + v.z * v.z + v.w * v.w;
    #pragma unroll
    for (int off = 16; off; off >>= 1) ss += __shfl_xor_sync(0xffffffffu, ss, off);
    if ((tid & 31) == 0) red[tid >> 5] = ss;
    __syncthreads();
    if (tid == 0) {
        float s = 0.f;
        #pragma unroll
        for (int i = 0; i < 8; i++) s += red[i];
        s_inv = rsqrtf(s / (float)H_DIM + 1e-6f);
    }
    __syncthreads();
    float inv = s_inv;
    const float4* wp = (const float4*)w;
    float4 wv = wp[tid];
    float4 o;
    o.x = v.x * inv * wv.x; o.y = v.y * inv * wv.y;
    o.z = v.z * inv * wv.z; o.w = v.w * inv * wv.w;
    ((float4*)(y + (size_t)t * H_DIM))[tid] = o;
}

// ---------------- generic SGEMM 128x128x16, 256 thr, 8x8 micro-tile ----------------
// MODE 0: C = A@B            MODE 1: C = Cadd + A@B
// MODE 2: per-expert gather: A rows via asg_tok[e*TCAP+r], B += e*K*N, C seg e*TCAP
// MODE 3: per-expert scatter: A row = e*TCAP+r, B += e*K*N, atomicAdd C[tok]*w
template<int MODE>
__global__ void gemm_kernel(const float* __restrict__ A, const float* __restrict__ B,
                            float* __restrict__ C, const float* __restrict__ Cadd,
                            const int* __restrict__ cnts,
                            const int* __restrict__ asg_tok,
                            const float* __restrict__ asg_w,
                            int M, int N, int K)
{
    __shared__ float As[16][132];
    __shared__ float Bs[16][128];
    int e = 0;
    int Mloc = M;
    if (MODE >= 2) {
        e = blockIdx.z;
        Mloc = cnts[e];
        B += (size_t)e * K * N;
    }
    int m0 = blockIdx.y * 128;
    int n0 = blockIdx.x * 128;
    if (m0 >= Mloc) return;
    int tid = threadIdx.x;
    int arow = tid >> 2;
    int acol = (tid & 3) << 2;
    const float* pa0 = nullptr;
    const float* pa1 = nullptr;
    {
        int r0 = m0 + arow, r1 = m0 + arow + 64;
        if (r0 < Mloc) {
            int g = (MODE == 2) ? asg_tok[e * TCAP + r0] : ((MODE == 3) ? (e * TCAP + r0) : r0);
            pa0 = A + (size_t)g * K + acol;
        }
        if (r1 < Mloc) {
            int g = (MODE == 2) ? asg_tok[e * TCAP + r1] : ((MODE == 3) ? (e * TCAP + r1) : r1);
            pa1 = A + (size_t)g * K + acol;
        }
    }
    int brow = tid >> 5;
    int bcol = (tid & 31) << 2;
    const float* pb = B + (size_t)brow * N + n0 + bcol;
    int ty = tid >> 4, tx = tid & 15;
    float acc[8][8];
    #pragma unroll
    for (int i = 0; i < 8; i++)
        #pragma unroll
        for (int j = 0; j < 8; j++) acc[i][j] = 0.f;

    for (int k0 = 0; k0 < K; k0 += 16) {
        float4 a0 = pa0 ? *(const float4*)(pa0 + k0) : make_float4(0.f, 0.f, 0.f, 0.f);
        float4 a1 = pa1 ? *(const float4*)(pa1 + k0) : make_float4(0.f, 0.f, 0.f, 0.f);
        float4 b0 = *(const float4*)(pb + (size_t)k0 * N);
        float4 b1 = *(const float4*)(pb + (size_t)(k0 + 8) * N);
        __syncthreads();
        As[acol + 0][arow] = a0.x; As[acol + 1][arow] = a0.y;
        As[acol + 2][arow] = a0.z; As[acol + 3][arow] = a0.w;
        As[acol + 0][arow + 64] = a1.x; As[acol + 1][arow + 64] = a1.y;
        As[acol + 2][arow + 64] = a1.z; As[acol + 3][arow + 64] = a1.w;
        *(float4*)&Bs[brow][bcol] = b0;
        *(float4*)&Bs[brow + 8][bcol] = b1;
        __syncthreads();
        #pragma unroll
        for (int kk = 0; kk < 16; kk++) {
            float ra[8], rb[8];
            *(float4*)&ra[0] = *(const float4*)&As[kk][ty * 8];
            *(float4*)&ra[4] = *(const float4*)&As[kk][ty * 8 + 4];
            *(float4*)&rb[0] = *(const float4*)&Bs[kk][tx * 8];
            *(float4*)&rb[4] = *(const float4*)&Bs[kk][tx * 8 + 4];
            #pragma unroll
            for (int i = 0; i < 8; i++)
                #pragma unroll
                for (int j = 0; j < 8; j++)
                    acc[i][j] = fmaf(ra[i], rb[j], acc[i][j]);
        }
    }
    #pragma unroll
    for (int i = 0; i < 8; i++) {
        int row = m0 + ty * 8 + i;
        if (row >= Mloc) continue;
        if (MODE == 3) {
            int tok = asg_tok[e * TCAP + row];
            float w = asg_w[e * TCAP + row];
            float* cp = C + (size_t)tok * N + n0 + tx * 8;
            #pragma unroll
            for (int j = 0; j < 8; j++) atomicAdd(cp + j, w * acc[i][j]);
        } else {
            size_t crow = (MODE == 2) ? ((size_t)(e * TCAP) + row) : (size_t)row;
            float* cp = C + crow * N + n0 + tx * 8;
            if (MODE == 1) {
                const float* ap = Cadd + (size_t)row * N + n0 + tx * 8;
                #pragma unroll
                for (int j = 0; j < 8; j++) cp[j] = ap[j] + acc[i][j];
            } else {
                #pragma unroll
                for (int j = 0; j < 8; j++) cp[j] = acc[i][j];
            }
        }
    }
}

// ---------------- RoPE (in-place on g_q/g_k) ----------------
__global__ void rope_kernel(const int* __restrict__ pos_ids)
{
    int t = blockIdx.x;
    float p = (float)pos_ids[t];
    const float c_l2 = -19.93156856932417f / 32.f;  // -log2(1e6)/32
    for (int i = threadIdx.x; i < (NH + NKV) * 32; i += blockDim.x) {
        float* base;
        int d;
        if (i < NH * 32) {
            base = g_q + (size_t)t * NH * HD + (size_t)(i >> 5) * HD;
            d = i & 31;
        } else {
            int j = i - NH * 32;
            base = g_k + (size_t)t * NKV * HD + (size_t)(j >> 5) * HD;
            d = j & 31;
        }
        float f = p * exp2f((float)d * c_l2);
        float sn, cs;
        sincosf(f, &sn, &cs);
        float a = base[d], b2 = base[d + 32];
        base[d] = a * cs - b2 * sn;
        base[d + 32] = b2 * cs + a * sn;
    }
}

// ---------------- flash attention, 64x64 tiles, causal ----------------
#define AT_S 68
#define ATT_SMEM (3 * 64 * AT_S * 4)
__global__ void attn_kernel()
{
    extern __shared__ float sm[];
    float* Qs = sm;                 // [64][AT_S]
    float* KVs = sm + 64 * AT_S;    // K then V (reused)
    float* Ps = sm + 2 * 64 * AT_S;
    const int qi = blockIdx.x, h = blockIdx.y, b = blockIdx.z;
    const int kvh = h >> 2;
    const int tid = threadIdx.x;
    const int r = tid >> 2, c = tid & 3;
    {
        int row = tid >> 2, cb = (tid & 3) << 4;
        const float4* src = (const float4*)(g_q + ((size_t)(b * S_LEN + qi * 64 + row)) * (NH * HD) + h * HD + cb);
        float4* dst = (float4*)(Qs + row * AT_S + cb);
        dst[0] = src[0]; dst[1] = src[1]; dst[2] = src[2]; dst[3] = src[3];
    }
    float m_r = -1e30f, l_r = 0.f;
    float acc[16];
    #pragma unroll
    for (int i = 0; i < 16; i++) acc[i] = 0.f;
    const int qg = qi * 64 + r;

    for (int j = 0; j <= qi; j++) {
        __syncthreads();
        {   // load K tile
            int row = tid >> 2, cb = (tid & 3) << 4;
            const float4* src = (const float4*)(g_k + ((size_t)(b * S_LEN + j * 64 + row)) * (NKV * HD) + kvh * HD + cb);
            float4* dst = (float4*)(KVs + row * AT_S + cb);
            dst[0] = src[0]; dst[1] = src[1]; dst[2] = src[2]; dst[3] = src[3];
        }
        __syncthreads();
        float s[16];
        const float4* qp = (const float4*)(Qs + r * AT_S);
        #pragma unroll
        for (int jj = 0; jj < 16; jj++) {
            int kt = (c << 4) + jj;
            const float4* kp = (const float4*)(KVs + kt * AT_S);
            float d = 0.f;
            #pragma unroll
            for (int k4 = 0; k4 < 16; k4++) {
                float4 qv = qp[k4], kv = kp[k4];
                d += qv.x * kv.x + qv.y * kv.y + qv.z * kv.z + qv.w * kv.w;
            }
            s[jj] = d * 0.125f;
        }
        if (j == qi) {
            #pragma unroll
            for (int jj = 0; jj < 16; jj++)
                if ((j << 6) + (c << 4) + jj > qg) s[jj] = -1e30f;
        }
        float mx = s[0];
        #pragma unroll
        for (int jj = 1; jj < 16; jj++) mx = fmaxf(mx, s[jj]);
        mx = fmaxf(mx, __shfl_xor_sync(0xffffffffu, mx, 1));
        mx = fmaxf(mx, __shfl_xor_sync(0xffffffffu, mx, 2));
        float m_new = fmaxf(m_r, mx);
        float alpha = __expf(m_r - m_new);
        float ls = 0.f;
        #pragma unroll
        for (int jj = 0; jj < 16; jj++) {
            float pv = __expf(s[jj] - m_new);
            s[jj] = pv;
            ls += pv;
        }
        ls += __shfl_xor_sync(0xffffffffu, ls, 1);
        ls += __shfl_xor_sync(0xffffffffu, ls, 2);
        l_r = l_r * alpha + ls;
        m_r = m_new;
        #pragma unroll
        for (int i = 0; i < 16; i++) acc[i] *= alpha;
        #pragma unroll
        for (int jj = 0; jj < 16; jj++) Ps[r * AT_S + (c << 4) + jj] = s[jj];
        __syncthreads();
        {   // load V tile (overwrite KVs)
            int row = tid >> 2, cb = (tid & 3) << 4;
            const float4* src = (const float4*)(g_v + ((size_t)(b * S_LEN + j * 64 + row)) * (NKV * HD) + kvh * HD + cb);
            float4* dst = (float4*)(KVs + row * AT_S + cb);
            dst[0] = src[0]; dst[1] = src[1]; dst[2] = src[2]; dst[3] = src[3];
        }
        __syncthreads();
        #pragma unroll 4
        for (int k = 0; k < 64; k++) {
            float pv = Ps[r * AT_S + k];
            const float4* vp = (const float4*)(KVs + k * AT_S + (c << 4));
            float4 v0 = vp[0], v1 = vp[1], v2 = vp[2], v3 = vp[3];
            acc[0] += pv * v0.x; acc[1] += pv * v0.y; acc[2] += pv * v0.z; acc[3] += pv * v0.w;
            acc[4] += pv * v1.x; acc[5] += pv * v1.y; acc[6] += pv * v1.z; acc[7] += pv * v1.w;
            acc[8] += pv * v2.x; acc[9] += pv * v2.y; acc[10] += pv * v2.z; acc[11] += pv * v2.w;
            acc[12] += pv * v3.x; acc[13] += pv * v3.y; acc[14] += pv * v3.z; acc[15] += pv * v3.w;
        }
    }
    float inv = 1.f / l_r;
    float4* op = (float4*)(g_attn + ((size_t)(b * S_LEN + qg)) * (NH * HD) + h * HD + (c << 4));
    #pragma unroll
    for (int i = 0; i < 4; i++) {
        float4 o;
        o.x = acc[i * 4 + 0] * inv; o.y = acc[i * 4 + 1] * inv;
        o.z = acc[i * 4 + 2] * inv; o.w = acc[i * 4 + 3] * inv;
        op[i] = o;
    }
}

// ---------------- router: softmax + top2 + assignment lists ----------------
__global__ void router_kernel(const float* __restrict__ rw)
{
    int warp = threadIdx.x >> 5, lane = threadIdx.x & 31;
    int t = blockIdx.x * 8 + warp;
    const float* xr = g_x2 + (size_t)t * H_DIM;
    float a[8];
    #pragma unroll
    for (int i = 0; i < 8; i++) a[i] = 0.f;
    for (int k = lane; k < H_DIM; k += 32) {
        float xv = xr[k];
        const float4* wp = (const float4*)(rw + (size_t)k * 8);
        float4 w0 = wp[0], w1 = wp[1];
        a[0] += xv * w0.x; a[1] += xv * w0.y; a[2] += xv * w0.z; a[3] += xv * w0.w;
        a[4] += xv * w1.x; a[5] += xv * w1.y; a[6] += xv * w1.z; a[7] += xv * w1.w;
    }
    #pragma unroll
    for (int off = 16; off; off >>= 1)
        #pragma unroll
        for (int i = 0; i < 8; i++) a[i] += __shfl_xor_sync(0xffffffffu, a[i], off);
    if (lane == 0) {
        float mx = a[0];
        #pragma unroll
        for (int i = 1; i < 8; i++) mx = fmaxf(mx, a[i]);
        float p[8], sum = 0.f;
        #pragma unroll
        for (int i = 0; i < 8; i++) { p[i] = expf(a[i] - mx); sum += p[i]; }
        float inv = 1.f / sum;
        #pragma unroll
        for (int i = 0; i < 8; i++) { p[i] *= inv; g_probs[t * 8 + i] = p[i]; }
        int i1 = 0; float v1 = p[0];
        #pragma unroll
        for (int i = 1; i < 8; i++) if (p[i] > v1) { v1 = p[i]; i1 = i; }
        int i2 = -1; float v2 = -1.f;
        #pragma unroll
        for (int i = 0; i < 8; i++) if (i != i1 && p[i] > v2) { v2 = p[i]; i2 = i; }
        int s1 = atomicAdd(&g_cnt[i1], 1);
        g_asg_tok[i1 * TCAP + s1] = t; g_asg_w[i1 * TCAP + s1] = v1;
        int s2 = atomicAdd(&g_cnt[i2], 1);
        g_asg_tok[i2 * TCAP + s2] = t; g_asg_w[i2 * TCAP + s2] = v2;
    }
}

// ---------------- silu(G)*U in place (G) ----------------
__global__ void silumul_kernel(int use_cnt)
{
    int e = blockIdx.y;
    int row = blockIdx.x;
    if (use_cnt && row >= g_cnt[e]) return;
    float* gp = g_G + ((size_t)e * TCAP + row) * I_DIM;
    const float* up = g_U + ((size_t)e * TCAP + row) * I_DIM;
    for (int i = threadIdx.x; i < I_DIM; i += blockDim.x) {
        float g = gp[i];
        gp[i] = (g / (1.f + expf(-g))) * up[i];
    }
}

// ---------------- shared-expert sigmoid gate ----------------
__global__ void sgate_kernel(const float* __restrict__ segw)
{
    int warp = threadIdx.x >> 5, lane = threadIdx.x & 31;
    int t = blockIdx.x * 8 + warp;
    const float* xr = g_x2 + (size_t)t * H_DIM;
    float a = 0.f;
    for (int k = lane; k < H_DIM; k += 32) a += xr[k] * segw[k];
    #pragma unroll
    for (int off = 16; off; off >>= 1) a += __shfl_xor_sync(0xffffffffu, a, off);
    if (lane == 0) g_sgate[t] = 1.f / (1.f + expf(-a));
}

// ---------------- final combine: out = resid + moe + sgate*sharedY ----------------
__global__ void combine_kernel(float* __restrict__ out)
{
    int i = blockIdx.x * blockDim.x + threadIdx.x;
    if (i < T_TOK * H_DIM)
        out[i] = g_resid[i] + g_moe[i] + g_sgate[i >> 10] * g_x1[i];
}

// ---------------- aux loss: deterministic reduction ----------------
__global__ void aux_kernel(float* __restrict__ out_aux)
{
    __shared__ float sm[256];
    int tid = threadIdx.x;
    int e = tid & 7;
    int chunk = tid >> 3;   // 0..31
    float s = 0.f;
    for (int t = chunk; t < T_TOK; t += 32) s += g_probs[t * 8 + e];
    sm[tid] = s;
    __syncthreads();
    for (int st = 16; st >= 1; st >>= 1) {
        if (chunk < st) sm[tid] += sm[tid + st * 8];
        __syncthreads();
    }
    if (tid == 0) {
        float aux = 0.f;
        #pragma unroll
        for (int i = 0; i < 8; i++) {
            float m = sm[i] / (float)T_TOK - 0.125f;
            aux += m * m;
        }
        out_aux[0] = aux / 8.f;
    }
}

// ---------------- launch ----------------
extern "C" void kernel_launch(void* const* d_in, const int* in_sizes, int n_in,
                              void* d_out, int out_size)
{
    const float* hidden = (const float*)d_in[0];
    // d_in[1] = attention_mask (pure causal -1e9; applied analytically)
    const int*   pos    = (const int*)d_in[2];
    const float* ln1    = (const float*)d_in[3];
    const float* ln2    = (const float*)d_in[4];
    const float* wq     = (const float*)d_in[5];
    const float* wk     = (const float*)d_in[6];
    const float* wv     = (const float*)d_in[7];
    const float* wo     = (const float*)d_in[8];
    const float* rw     = (const float*)d_in[9];
    const float* egw    = (const float*)d_in[10];
    const float* euw    = (const float*)d_in[11];
    const float* edw    = (const float*)d_in[12];
    const float* sgw    = (const float*)d_in[13];
    const float* suw    = (const float*)d_in[14];
    const float* sdw    = (const float*)d_in[15];
    const float* segw   = (const float*)d_in[16];
    float* out = (float*)d_out;

    float *x1, *q, *k, *v, *attn, *resid, *x2, *moe, *G, *U, *asw;
    int *cnt, *ast;
    cudaGetSymbolAddress((void**)&x1, g_x1);
    cudaGetSymbolAddress((void**)&q, g_q);
    cudaGetSymbolAddress((void**)&k, g_k);
    cudaGetSymbolAddress((void**)&v, g_v);
    cudaGetSymbolAddress((void**)&attn, g_attn);
    cudaGetSymbolAddress((void**)&resid, g_resid);
    cudaGetSymbolAddress((void**)&x2, g_x2);
    cudaGetSymbolAddress((void**)&moe, g_moe);
    cudaGetSymbolAddress((void**)&G, g_G);
    cudaGetSymbolAddress((void**)&U, g_U);
    cudaGetSymbolAddress((void**)&cnt, g_cnt);
    cudaGetSymbolAddress((void**)&ast, g_asg_tok);
    cudaGetSymbolAddress((void**)&asw, g_asg_w);

    cudaFuncSetAttribute((const void*)attn_kernel,
                         cudaFuncAttributeMaxDynamicSharedMemorySize, ATT_SMEM);

    zero_kernel<<<(T_TOK * H_DIM + 255) / 256, 256>>>();

    // attention block
    rmsnorm_kernel<<<T_TOK, 256>>>(hidden, ln1, x1);
    gemm_kernel<0><<<dim3(8, 16), 256>>>(x1, wq, q, nullptr, nullptr, nullptr, nullptr, T_TOK, 1024, 1024);
    gemm_kernel<0><<<dim3(2, 16), 256>>>(x1, wk, k, nullptr, nullptr, nullptr, nullptr, T_TOK, 256, 1024);
    gemm_kernel<0><<<dim3(2, 16), 256>>>(x1, wv, v, nullptr, nullptr, nullptr, nullptr, T_TOK, 256, 1024);
    rope_kernel<<<T_TOK, 256>>>(pos);
    attn_kernel<<<dim3(16, NH, B_SZ), 256, ATT_SMEM>>>();
    gemm_kernel<1><<<dim3(8, 16), 256>>>(attn, wo, resid, hidden, nullptr, nullptr, nullptr, T_TOK, 1024, 1024);

    // MoE block
    rmsnorm_kernel<<<T_TOK, 256>>>(resid, ln2, x2);
    router_kernel<<<T_TOK / 8, 256>>>(rw);
    gemm_kernel<2><<<dim3(8, 16, NE), 256>>>(x2, egw, G, nullptr, cnt, ast, nullptr, TCAP, 1024, 1024);
    gemm_kernel<2><<<dim3(8, 16, NE), 256>>>(x2, euw, U, nullptr, cnt, ast, nullptr, TCAP, 1024, 1024);
    silumul_kernel<<<dim3(TCAP, NE), 256>>>(1);
    gemm_kernel<3><<<dim3(8, 16, NE), 256>>>(G, edw, moe, nullptr, cnt, ast, asw, TCAP, 1024, 1024);

    // shared expert (reuses G/U segment 0 after routed path consumed them)
    gemm_kernel<0><<<dim3(8, 16), 256>>>(x2, sgw, G, nullptr, nullptr, nullptr, nullptr, T_TOK, 1024, 1024);
    gemm_kernel<0><<<dim3(8, 16), 256>>>(x2, suw, U, nullptr, nullptr, nullptr, nullptr, T_TOK, 1024, 1024);
    silumul_kernel<<<dim3(T_TOK, 1), 256>>>(0);
    gemm_kernel<0><<<dim3(8, 16), 256>>>(G, sdw, x1, nullptr, nullptr, nullptr, nullptr, T_TOK, 1024, 1024);
    sgate_kernel<<<T_TOK / 8, 256>>>(segw);

    combine_kernel<<<(T_TOK * H_DIM + 255) / 256, 256>>>(out);
    if (out_size > T_TOK * H_DIM)
        aux_kernel<<<1, 256>>>(out + (out_size - 1));
}

// round 10
// speedup vs baseline: 1.7499x; 1.7499x over previous
#include <cuda_runtime.h>
#include <cuda_bf16.h>
#include <math.h>
#include <stdint.h>

#define T_TOK 2048
#define H_DIM 1024
#define I_DIM 1024
#define S_LEN 1024
#define B_SZ  2
#define NH    16
#define NKV   4
#define HD    64
#define NE    8
#define TCAP  2048
#define QKV_N 1536   // 1024 q + 256 k + 256 v

// ---------------- scratch ----------------
__device__ float g_x1[T_TOK * H_DIM];        // rmsnorm1 out, later reused as sharedY
__device__ float g_qkv[T_TOK * QKV_N];
__device__ float g_attn[T_TOK * NH * HD];
__device__ float g_resid[T_TOK * H_DIM];
__device__ float g_x2[T_TOK * H_DIM];
__device__ float g_moe[T_TOK * H_DIM];
__device__ float g_G[NE * TCAP * I_DIM];
__device__ float g_U[NE * TCAP * I_DIM];
__device__ float g_wqkv[H_DIM * QKV_N];
__device__ float g_probs[T_TOK * NE];
__device__ int   g_cnt[NE];
__device__ int   g_asg_tok[NE * TCAP];
__device__ float g_asg_w[NE * TCAP];
__device__ float g_sgate[T_TOK];

// ---------------- zero (inside graph; replays need fresh state) ----------------
__global__ void zero_kernel()
{
    int i = blockIdx.x * blockDim.x + threadIdx.x;
    if (i < T_TOK * H_DIM) g_moe[i] = 0.f;
    if (i < NE) g_cnt[i] = 0;
}

// ---------------- concat wq|wk|wv -> g_wqkv [H][1536] ----------------
__global__ void concat_qkv_w(const float* __restrict__ wq, const float* __restrict__ wk,
                             const float* __restrict__ wv)
{
    int idx = blockIdx.x * blockDim.x + threadIdx.x;
    if (idx >= H_DIM * QKV_N) return;
    int r = idx / QKV_N, c = idx - r * QKV_N;
    float v;
    if (c < 1024)      v = wq[r * 1024 + c];
    else if (c < 1280) v = wk[r * 256 + (c - 1024)];
    else               v = wv[r * 256 + (c - 1280)];
    g_wqkv[idx] = v;
}

// ---------------- RMSNorm ----------------
__global__ void rmsnorm_kernel(const float* __restrict__ x, const float* __restrict__ w,
                               float* __restrict__ y)
{
    __shared__ float red[8];
    __shared__ float s_inv;
    int t = blockIdx.x;
    int tid = threadIdx.x;
    const float4* xp = (const float4*)(x + (size_t)t * H_DIM);
    float4 v = xp[tid];
    float ss = v.x * v.x + v.y * v.y + v.z * v.z + v.w * v.w;
    #pragma unroll
    for (int off = 16; off; off >>= 1) ss += __shfl_xor_sync(0xffffffffu, ss, off);
    if ((tid & 31) == 0) red[tid >> 5] = ss;
    __syncthreads();
    if (tid == 0) {
        float s = 0.f;
        #pragma unroll
        for (int i = 0; i < 8; i++) s += red[i];
        s_inv = rsqrtf(s / (float)H_DIM + 1e-6f);
    }
    __syncthreads();
    float inv = s_inv;
    const float4* wp = (const float4*)w;
    float4 wv = wp[tid];
    float4 o;
    o.x = v.x * inv * wv.x; o.y = v.y * inv * wv.y;
    o.z = v.z * inv * wv.z; o.w = v.w * inv * wv.w;
    ((float4*)(y + (size_t)t * H_DIM))[tid] = o;
}

// ---------------- tf32 tensor-core GEMM 128x128x16, 256 thr, mma.m16n8k8 ----------------
// MODE 0: C = A@B            MODE 1: C = Cadd + A@B
// MODE 2: per-expert gather rows of A via asg_tok; C row = e*TCAP + local
// MODE 3: per-expert A row = e*TCAP+local; atomicAdd into C[tok] scaled by asg_w
__device__ __forceinline__ uint32_t f2tf(float x)
{
    uint32_t u;
    asm("cvt.rna.tf32.f32 %0, %1;" : "=r"(u) : "f"(x));
    return u;
}

template<int MODE>
__global__ __launch_bounds__(256)
void gemm_tc(const float* __restrict__ A, const float* __restrict__ B,
             float* __restrict__ C, const float* __restrict__ Cadd,
             const int* __restrict__ cnts, const int* __restrict__ asg_tok,
             const float* __restrict__ asg_w, int M, int N, int K)
{
    __shared__ uint32_t As[2][16][136];   // K-major: As[k][m], stride 136 -> conflict-free frags
    __shared__ uint32_t Bs[2][16][136];   // Bs[k][n]
    int e = 0;
    int Mloc = M;
    if (MODE >= 2) {
        e = blockIdx.z;
        Mloc = cnts[e];
        B += (size_t)e * K * N;
    }
    int m0 = blockIdx.y * 128;
    int n0 = blockIdx.x * 128;
    if (m0 >= Mloc) return;

    const int tid = threadIdx.x;
    const int lane = tid & 31;
    const int warp = tid >> 5;
    const int gid = lane >> 2, tig = lane & 3;
    const int wm = (warp >> 2) * 64;     // 2 warps along M
    const int wn = (warp & 3) * 32;      // 4 warps along N

    // --- loader setup ---
    int a_am[2], a_ak[2];
    const float* a_p[2];
    #pragma unroll
    for (int i = 0; i < 2; i++) {
        int idx = tid + i * 256;
        a_am[i] = idx >> 2;
        a_ak[i] = (idx & 3) << 2;
        int row = m0 + a_am[i];
        a_p[i] = nullptr;
        if (row < Mloc) {
            int g = (MODE == 2) ? asg_tok[e * TCAP + row]
                  : ((MODE == 3) ? (e * TCAP + row) : row);
            a_p[i] = A + (size_t)g * K + a_ak[i];
        }
    }
    int b_bk[2], b_bn[2];
    const float* b_p[2];
    #pragma unroll
    for (int i = 0; i < 2; i++) {
        int idx = tid + i * 256;
        b_bk[i] = idx >> 5;
        b_bn[i] = (idx & 31) << 2;
        b_p[i] = B + (size_t)b_bk[i] * N + n0 + b_bn[i];
    }

    float acc[4][4][4];
    #pragma unroll
    for (int mf = 0; mf < 4; mf++)
        #pragma unroll
        for (int nf = 0; nf < 4; nf++)
            #pragma unroll
            for (int r = 0; r < 4; r++) acc[mf][nf][r] = 0.f;

    float4 fa[2], fb[2];
    #pragma unroll
    for (int i = 0; i < 2; i++) {
        fa[i] = a_p[i] ? *(const float4*)(a_p[i]) : make_float4(0.f, 0.f, 0.f, 0.f);
        fb[i] = *(const float4*)(b_p[i]);
    }

    for (int k0 = 0; k0 < K; k0 += 16) {
        int buf = (k0 >> 4) & 1;
        #pragma unroll
        for (int i = 0; i < 2; i++) {
            As[buf][a_ak[i] + 0][a_am[i]] = f2tf(fa[i].x);
            As[buf][a_ak[i] + 1][a_am[i]] = f2tf(fa[i].y);
            As[buf][a_ak[i] + 2][a_am[i]] = f2tf(fa[i].z);
            As[buf][a_ak[i] + 3][a_am[i]] = f2tf(fa[i].w);
            uint4 bv;
            bv.x = f2tf(fb[i].x); bv.y = f2tf(fb[i].y);
            bv.z = f2tf(fb[i].z); bv.w = f2tf(fb[i].w);
            *(uint4*)&Bs[buf][b_bk[i]][b_bn[i]] = bv;
        }
        __syncthreads();
        if (k0 + 16 < K) {
            #pragma unroll
            for (int i = 0; i < 2; i++) {
                fa[i] = a_p[i] ? *(const float4*)(a_p[i] + k0 + 16)
                               : make_float4(0.f, 0.f, 0.f, 0.f);
                fb[i] = *(const float4*)(b_p[i] + (size_t)(k0 + 16) * N);
            }
        }
        #pragma unroll
        for (int ks = 0; ks < 16; ks += 8) {
            uint32_t af[4][4], bf[4][2];
            #pragma unroll
            for (int mf = 0; mf < 4; mf++) {
                int mb = wm + mf * 16 + gid;
                af[mf][0] = As[buf][ks + tig][mb];
                af[mf][1] = As[buf][ks + tig][mb + 8];
                af[mf][2] = As[buf][ks + tig + 4][mb];
                af[mf][3] = As[buf][ks + tig + 4][mb + 8];
            }
            #pragma unroll
            for (int nf = 0; nf < 4; nf++) {
                int nb = wn + nf * 8 + gid;
                bf[nf][0] = Bs[buf][ks + tig][nb];
                bf[nf][1] = Bs[buf][ks + tig + 4][nb];
            }
            #pragma unroll
            for (int mf = 0; mf < 4; mf++)
                #pragma unroll
                for (int nf = 0; nf < 4; nf++)
                    asm volatile(
                        "mma.sync.aligned.m16n8k8.row.col.f32.tf32.tf32.f32 "
                        "{%0,%1,%2,%3},{%4,%5,%6,%7},{%8,%9},{%0,%1,%2,%3};"
                        : "+f"(acc[mf][nf][0]), "+f"(acc[mf][nf][1]),
                          "+f"(acc[mf][nf][2]), "+f"(acc[mf][nf][3])
                        : "r"(af[mf][0]), "r"(af[mf][1]), "r"(af[mf][2]), "r"(af[mf][3]),
                          "r"(bf[nf][0]), "r"(bf[nf][1]));
        }
        __syncthreads();
    }

    // --- epilogue ---
    #pragma unroll
    for (int mf = 0; mf < 4; mf++) {
        int r0 = m0 + wm + mf * 16 + gid;
        int r1 = r0 + 8;
        #pragma unroll
        for (int nf = 0; nf < 4; nf++) {
            int col = n0 + wn + nf * 8 + tig * 2;
            if (MODE == 3) {
                if (r0 < Mloc) {
                    int tok = asg_tok[e * TCAP + r0];
                    float w = asg_w[e * TCAP + r0];
                    float* cp = C + (size_t)tok * N + col;
                    atomicAdd(cp, w * acc[mf][nf][0]);
                    atomicAdd(cp + 1, w * acc[mf][nf][1]);
                }
                if (r1 < Mloc) {
                    int tok = asg_tok[e * TCAP + r1];
                    float w = asg_w[e * TCAP + r1];
                    float* cp = C + (size_t)tok * N + col;
                    atomicAdd(cp, w * acc[mf][nf][2]);
                    atomicAdd(cp + 1, w * acc[mf][nf][3]);
                }
            } else {
                if (r0 < Mloc) {
                    size_t cr = (MODE == 2) ? (size_t)(e * TCAP + r0) : (size_t)r0;
                    float2 v = make_float2(acc[mf][nf][0], acc[mf][nf][1]);
                    if (MODE == 1) {
                        float2 av = *(const float2*)(Cadd + (size_t)r0 * N + col);
                        v.x += av.x; v.y += av.y;
                    }
                    *(float2*)(C + cr * N + col) = v;
                }
                if (r1 < Mloc) {
                    size_t cr = (MODE == 2) ? (size_t)(e * TCAP + r1) : (size_t)r1;
                    float2 v = make_float2(acc[mf][nf][2], acc[mf][nf][3]);
                    if (MODE == 1) {
                        float2 av = *(const float2*)(Cadd + (size_t)r1 * N + col);
                        v.x += av.x; v.y += av.y;
                    }
                    *(float2*)(C + cr * N + col) = v;
                }
            }
        }
    }
}

// ---------------- RoPE (in-place on g_qkv) ----------------
__global__ void rope_kernel(const int* __restrict__ pos_ids)
{
    int t = blockIdx.x;
    float p = (float)pos_ids[t];
    const float c_l2 = -19.93156856932417f / 32.f;  // -log2(1e6)/32
    float* row = g_qkv + (size_t)t * QKV_N;
    for (int i = threadIdx.x; i < (NH + NKV) * 32; i += blockDim.x) {
        float* base;
        int d;
        if (i < NH * 32) {
            base = row + (size_t)(i >> 5) * HD;          // q heads
            d = i & 31;
        } else {
            int j = i - NH * 32;
            base = row + 1024 + (size_t)(j >> 5) * HD;   // k heads
            d = j & 31;
        }
        float f = p * exp2f((float)d * c_l2);
        float sn, cs;
        sincosf(f, &sn, &cs);
        float a = base[d], b2 = base[d + 32];
        base[d] = a * cs - b2 * sn;
        base[d + 32] = b2 * cs + a * sn;
    }
}

// ---------------- flash attention, 64x64 tiles, causal ----------------
#define AT_S 68
#define ATT_SMEM (3 * 64 * AT_S * 4)
__global__ void attn_kernel()
{
    extern __shared__ float sm[];
    float* Qs = sm;
    float* KVs = sm + 64 * AT_S;
    float* Ps = sm + 2 * 64 * AT_S;
    const int qi = blockIdx.x, h = blockIdx.y, b = blockIdx.z;
    const int kvh = h >> 2;
    const int tid = threadIdx.x;
    const int r = tid >> 2, c = tid & 3;
    {
        int row = tid >> 2, cb = (tid & 3) << 4;
        const float4* src = (const float4*)(g_qkv + ((size_t)(b * S_LEN + qi * 64 + row)) * QKV_N + h * HD + cb);
        float4* dst = (float4*)(Qs + row * AT_S + cb);
        dst[0] = src[0]; dst[1] = src[1]; dst[2] = src[2]; dst[3] = src[3];
    }
    float m_r = -1e30f, l_r = 0.f;
    float acc[16];
    #pragma unroll
    for (int i = 0; i < 16; i++) acc[i] = 0.f;
    const int qg = qi * 64 + r;

    for (int j = 0; j <= qi; j++) {
        __syncthreads();
        {   // K tile
            int row = tid >> 2, cb = (tid & 3) << 4;
            const float4* src = (const float4*)(g_qkv + ((size_t)(b * S_LEN + j * 64 + row)) * QKV_N + 1024 + kvh * HD + cb);
            float4* dst = (float4*)(KVs + row * AT_S + cb);
            dst[0] = src[0]; dst[1] = src[1]; dst[2] = src[2]; dst[3] = src[3];
        }
        __syncthreads();
        float s[16];
        const float4* qp = (const float4*)(Qs + r * AT_S);
        #pragma unroll
        for (int jj = 0; jj < 16; jj++) {
            int kt = (c << 4) + jj;
            const float4* kp = (const float4*)(KVs + kt * AT_S);
            float d = 0.f;
            #pragma unroll
            for (int k4 = 0; k4 < 16; k4++) {
                float4 qv = qp[k4], kv = kp[k4];
                d += qv.x * kv.x + qv.y * kv.y + qv.z * kv.z + qv.w * kv.w;
            }
            s[jj] = d * 0.125f;
        }
        if (j == qi) {
            #pragma unroll
            for (int jj = 0; jj < 16; jj++)
                if ((j << 6) + (c << 4) + jj > qg) s[jj] = -1e30f;
        }
        float mx = s[0];
        #pragma unroll
        for (int jj = 1; jj < 16; jj++) mx = fmaxf(mx, s[jj]);
        mx = fmaxf(mx, __shfl_xor_sync(0xffffffffu, mx, 1));
        mx = fmaxf(mx, __shfl_xor_sync(0xffffffffu, mx, 2));
        float m_new = fmaxf(m_r, mx);
        float alpha = __expf(m_r - m_new);
        float ls = 0.f;
        #pragma unroll
        for (int jj = 0; jj < 16; jj++) {
            float pv = __expf(s[jj] - m_new);
            s[jj] = pv;
            ls += pv;
        }
        ls += __shfl_xor_sync(0xffffffffu, ls, 1);
        ls += __shfl_xor_sync(0xffffffffu, ls, 2);
        l_r = l_r * alpha + ls;
        m_r = m_new;
        #pragma unroll
        for (int i = 0; i < 16; i++) acc[i] *= alpha;
        #pragma unroll
        for (int jj = 0; jj < 16; jj++) Ps[r * AT_S + (c << 4) + jj] = s[jj];
        __syncthreads();
        {   // V tile
            int row = tid >> 2, cb = (tid & 3) << 4;
            const float4* src = (const float4*)(g_qkv + ((size_t)(b * S_LEN + j * 64 + row)) * QKV_N + 1280 + kvh * HD + cb);
            float4* dst = (float4*)(KVs + row * AT_S + cb);
            dst[0] = src[0]; dst[1] = src[1]; dst[2] = src[2]; dst[3] = src[3];
        }
        __syncthreads();
        #pragma unroll 4
        for (int k = 0; k < 64; k++) {
            float pv = Ps[r * AT_S + k];
            const float4* vp = (const float4*)(KVs + k * AT_S + (c << 4));
            float4 v0 = vp[0], v1 = vp[1], v2 = vp[2], v3 = vp[3];
            acc[0] += pv * v0.x; acc[1] += pv * v0.y; acc[2] += pv * v0.z; acc[3] += pv * v0.w;
            acc[4] += pv * v1.x; acc[5] += pv * v1.y; acc[6] += pv * v1.z; acc[7] += pv * v1.w;
            acc[8] += pv * v2.x; acc[9] += pv * v2.y; acc[10] += pv * v2.z; acc[11] += pv * v2.w;
            acc[12] += pv * v3.x; acc[13] += pv * v3.y; acc[14] += pv * v3.z; acc[15] += pv * v3.w;
        }
    }
    float inv = 1.f / l_r;
    float4* op = (float4*)(g_attn + ((size_t)(b * S_LEN + qg)) * (NH * HD) + h * HD + (c << 4));
    #pragma unroll
    for (int i = 0; i < 4; i++) {
        float4 o;
        o.x = acc[i * 4 + 0] * inv; o.y = acc[i * 4 + 1] * inv;
        o.z = acc[i * 4 + 2] * inv; o.w = acc[i * 4 + 3] * inv;
        op[i] = o;
    }
}

// ---------------- router: softmax + top2 + assignment lists ----------------
__global__ void router_kernel(const float* __restrict__ rw)
{
    int warp = threadIdx.x >> 5, lane = threadIdx.x & 31;
    int t = blockIdx.x * 8 + warp;
    const float* xr = g_x2 + (size_t)t * H_DIM;
    float a[8];
    #pragma unroll
    for (int i = 0; i < 8; i++) a[i] = 0.f;
    for (int k = lane; k < H_DIM; k += 32) {
        float xv = xr[k];
        const float4* wp = (const float4*)(rw + (size_t)k * 8);
        float4 w0 = wp[0], w1 = wp[1];
        a[0] += xv * w0.x; a[1] += xv * w0.y; a[2] += xv * w0.z; a[3] += xv * w0.w;
        a[4] += xv * w1.x; a[5] += xv * w1.y; a[6] += xv * w1.z; a[7] += xv * w1.w;
    }
    #pragma unroll
    for (int off = 16; off; off >>= 1)
        #pragma unroll
        for (int i = 0; i < 8; i++) a[i] += __shfl_xor_sync(0xffffffffu, a[i], off);
    if (lane == 0) {
        float mx = a[0];
        #pragma unroll
        for (int i = 1; i < 8; i++) mx = fmaxf(mx, a[i]);
        float p[8], sum = 0.f;
        #pragma unroll
        for (int i = 0; i < 8; i++) { p[i] = expf(a[i] - mx); sum += p[i]; }
        float inv = 1.f / sum;
        #pragma unroll
        for (int i = 0; i < 8; i++) { p[i] *= inv; g_probs[t * 8 + i] = p[i]; }
        int i1 = 0; float v1 = p[0];
        #pragma unroll
        for (int i = 1; i < 8; i++) if (p[i] > v1) { v1 = p[i]; i1 = i; }
        int i2 = -1; float v2 = -1.f;
        #pragma unroll
        for (int i = 0; i < 8; i++) if (i != i1 && p[i] > v2) { v2 = p[i]; i2 = i; }
        int s1 = atomicAdd(&g_cnt[i1], 1);
        g_asg_tok[i1 * TCAP + s1] = t; g_asg_w[i1 * TCAP + s1] = v1;
        int s2 = atomicAdd(&g_cnt[i2], 1);
        g_asg_tok[i2 * TCAP + s2] = t; g_asg_w[i2 * TCAP + s2] = v2;
    }
}

// ---------------- silu(G)*U in place (G) ----------------
__global__ void silumul_kernel(int use_cnt)
{
    int e = blockIdx.y;
    int row = blockIdx.x;
    if (use_cnt && row >= g_cnt[e]) return;
    float* gp = g_G + ((size_t)e * TCAP + row) * I_DIM;
    const float* up = g_U + ((size_t)e * TCAP + row) * I_DIM;
    for (int i = threadIdx.x; i < I_DIM; i += blockDim.x) {
        float g = gp[i];
        gp[i] = (g / (1.f + __expf(-g))) * up[i];
    }
}

// ---------------- shared-expert sigmoid gate ----------------
__global__ void sgate_kernel(const float* __restrict__ segw)
{
    int warp = threadIdx.x >> 5, lane = threadIdx.x & 31;
    int t = blockIdx.x * 8 + warp;
    const float* xr = g_x2 + (size_t)t * H_DIM;
    float a = 0.f;
    for (int k = lane; k < H_DIM; k += 32) a += xr[k] * segw[k];
    #pragma unroll
    for (int off = 16; off; off >>= 1) a += __shfl_xor_sync(0xffffffffu, a, off);
    if (lane == 0) g_sgate[t] = 1.f / (1.f + expf(-a));
}

// ---------------- final combine ----------------
__global__ void combine_kernel(float* __restrict__ out)
{
    int i = blockIdx.x * blockDim.x + threadIdx.x;
    if (i < T_TOK * H_DIM)
        out[i] = g_resid[i] + g_moe[i] + g_sgate[i >> 10] * g_x1[i];
}

// ---------------- aux loss ----------------
__global__ void aux_kernel(float* __restrict__ out_aux)
{
    __shared__ float sm[256];
    int tid = threadIdx.x;
    int e = tid & 7;
    int chunk = tid >> 3;
    float s = 0.f;
    for (int t = chunk; t < T_TOK; t += 32) s += g_probs[t * 8 + e];
    sm[tid] = s;
    __syncthreads();
    for (int st = 16; st >= 1; st >>= 1) {
        if (chunk < st) sm[tid] += sm[tid + st * 8];
        __syncthreads();
    }
    if (tid == 0) {
        float aux = 0.f;
        #pragma unroll
        for (int i = 0; i < 8; i++) {
            float m = sm[i] / (float)T_TOK - 0.125f;
            aux += m * m;
        }
        out_aux[0] = aux / 8.f;
    }
}

// ---------------- launch ----------------
extern "C" void kernel_launch(void* const* d_in, const int* in_sizes, int n_in,
                              void* d_out, int out_size)
{
    const float* hidden = (const float*)d_in[0];
    const int*   pos    = (const int*)d_in[2];
    const float* ln1    = (const float*)d_in[3];
    const float* ln2    = (const float*)d_in[4];
    const float* wq     = (const float*)d_in[5];
    const float* wk     = (const float*)d_in[6];
    const float* wv     = (const float*)d_in[7];
    const float* wo     = (const float*)d_in[8];
    const float* rw     = (const float*)d_in[9];
    const float* egw    = (const float*)d_in[10];
    const float* euw    = (const float*)d_in[11];
    const float* edw    = (const float*)d_in[12];
    const float* sgw    = (const float*)d_in[13];
    const float* suw    = (const float*)d_in[14];
    const float* sdw    = (const float*)d_in[15];
    const float* segw   = (const float*)d_in[16];
    float* out = (float*)d_out;

    float *x1, *qkv, *attn, *resid, *x2, *moe, *G, *U, *asw, *wqkv;
    int *cnt, *ast;
    cudaGetSymbolAddress((void**)&x1, g_x1);
    cudaGetSymbolAddress((void**)&qkv, g_qkv);
    cudaGetSymbolAddress((void**)&attn, g_attn);
    cudaGetSymbolAddress((void**)&resid, g_resid);
    cudaGetSymbolAddress((void**)&x2, g_x2);
    cudaGetSymbolAddress((void**)&moe, g_moe);
    cudaGetSymbolAddress((void**)&G, g_G);
    cudaGetSymbolAddress((void**)&U, g_U);
    cudaGetSymbolAddress((void**)&cnt, g_cnt);
    cudaGetSymbolAddress((void**)&ast, g_asg_tok);
    cudaGetSymbolAddress((void**)&asw, g_asg_w);
    cudaGetSymbolAddress((void**)&wqkv, g_wqkv);

    cudaFuncSetAttribute((const void*)attn_kernel,
                         cudaFuncAttributeMaxDynamicSharedMemorySize, ATT_SMEM);

    zero_kernel<<<(T_TOK * H_DIM + 255) / 256, 256>>>();
    concat_qkv_w<<<(H_DIM * QKV_N + 255) / 256, 256>>>(wq, wk, wv);

    // attention block
    rmsnorm_kernel<<<T_TOK, 256>>>(hidden, ln1, x1);
    gemm_tc<0><<<dim3(12, 16), 256>>>(x1, wqkv, qkv, nullptr, nullptr, nullptr, nullptr, T_TOK, QKV_N, 1024);
    rope_kernel<<<T_TOK, 256>>>(pos);
    attn_kernel<<<dim3(16, NH, B_SZ), 256, ATT_SMEM>>>();
    gemm_tc<1><<<dim3(8, 16), 256>>>(attn, wo, resid, hidden, nullptr, nullptr, nullptr, T_TOK, 1024, 1024);

    // MoE block
    rmsnorm_kernel<<<T_TOK, 256>>>(resid, ln2, x2);
    router_kernel<<<T_TOK / 8, 256>>>(rw);
    gemm_tc<2><<<dim3(8, 16, NE), 256>>>(x2, egw, G, nullptr, cnt, ast, nullptr, TCAP, 1024, 1024);
    gemm_tc<2><<<dim3(8, 16, NE), 256>>>(x2, euw, U, nullptr, cnt, ast, nullptr, TCAP, 1024, 1024);
    silumul_kernel<<<dim3(TCAP, NE), 256>>>(1);
    gemm_tc<3><<<dim3(8, 16, NE), 256>>>(G, edw, moe, nullptr, cnt, ast, asw, TCAP, 1024, 1024);

    // shared expert
    gemm_tc<0><<<dim3(8, 16), 256>>>(x2, sgw, G, nullptr, nullptr, nullptr, nullptr, T_TOK, 1024, 1024);
    gemm_tc<0><<<dim3(8, 16), 256>>>(x2, suw, U, nullptr, nullptr, nullptr, nullptr, T_TOK, 1024, 1024);
    silumul_kernel<<<dim3(T_TOK, 1), 256>>>(0);
    gemm_tc<0><<<dim3(8, 16), 256>>>(G, sdw, x1, nullptr, nullptr, nullptr, nullptr, T_TOK, 1024, 1024);
    sgate_kernel<<<T_TOK / 8, 256>>>(segw);

    combine_kernel<<<(T_TOK * H_DIM + 255) / 256, 256>>>(out);
    if (out_size > T_TOK * H_DIM)
        aux_kernel<<<1, 256>>>(out + (out_size - 1));
}

// round 12
// speedup vs baseline: 4.1102x; 2.3489x over previous
#include <cuda_runtime.h>
#include <cuda_bf16.h>
#include <math.h>
#include <stdint.h>

#define T_TOK 2048
#define H_DIM 1024
#define I_DIM 1024
#define S_LEN 1024
#define B_SZ  2
#define NH    16
#define NKV   4
#define HD    64
#define NE    8
#define TCAP  2048
#define QKV_N 1536   // 1024 q + 256 k + 256 v

// ---------------- scratch ----------------
__device__ float g_x1[T_TOK * H_DIM];        // rmsnorm1 out, later reused as sharedY
__device__ float g_qkv[T_TOK * QKV_N];
__device__ float g_attn[T_TOK * NH * HD];
__device__ float g_resid[T_TOK * H_DIM];
__device__ float g_x2[T_TOK * H_DIM];
__device__ float g_moe[T_TOK * H_DIM];
__device__ float g_G[NE * TCAP * I_DIM];
__device__ float g_U[NE * TCAP * I_DIM];
__device__ float g_wqkv[H_DIM * QKV_N];
__device__ float g_probs[T_TOK * NE];
__device__ int   g_cnt[NE];
__device__ int   g_asg_tok[NE * TCAP];
__device__ float g_asg_w[NE * TCAP];
__device__ float g_sgate[T_TOK];

__device__ __forceinline__ uint32_t f2tf(float x)
{
    uint32_t u;
    asm("cvt.rna.tf32.f32 %0, %1;" : "=r"(u) : "f"(x));
    return u;
}

__device__ __forceinline__ void mma_tf32(float* c, const uint32_t* a, uint32_t b0, uint32_t b1)
{
    asm volatile(
        "mma.sync.aligned.m16n8k8.row.col.f32.tf32.tf32.f32 "
        "{%0,%1,%2,%3},{%4,%5,%6,%7},{%8,%9},{%0,%1,%2,%3};"
        : "+f"(c[0]), "+f"(c[1]), "+f"(c[2]), "+f"(c[3])
        : "r"(a[0]), "r"(a[1]), "r"(a[2]), "r"(a[3]), "r"(b0), "r"(b1));
}

// ---------------- zero (inside graph; replays need fresh state) ----------------
__global__ void zero_kernel()
{
    int i = blockIdx.x * blockDim.x + threadIdx.x;
    if (i < T_TOK * H_DIM) g_moe[i] = 0.f;
    if (i < NE) g_cnt[i] = 0;
}

// ---------------- concat wq|wk|wv -> g_wqkv [H][1536] ----------------
__global__ void concat_qkv_w(const float* __restrict__ wq, const float* __restrict__ wk,
                             const float* __restrict__ wv)
{
    int idx = blockIdx.x * blockDim.x + threadIdx.x;
    if (idx >= H_DIM * QKV_N) return;
    int r = idx / QKV_N, c = idx - r * QKV_N;
    float v;
    if (c < 1024)      v = wq[r * 1024 + c];
    else if (c < 1280) v = wk[r * 256 + (c - 1024)];
    else               v = wv[r * 256 + (c - 1280)];
    g_wqkv[idx] = v;
}

// ---------------- RMSNorm ----------------
__global__ void rmsnorm_kernel(const float* __restrict__ x, const float* __restrict__ w,
                               float* __restrict__ y)
{
    __shared__ float red[8];
    __shared__ float s_inv;
    int t = blockIdx.x;
    int tid = threadIdx.x;
    const float4* xp = (const float4*)(x + (size_t)t * H_DIM);
    float4 v = xp[tid];
    float ss = v.x * v.x + v.y * v.y + v.z * v.z + v.w * v.w;
    #pragma unroll
    for (int off = 16; off; off >>= 1) ss += __shfl_xor_sync(0xffffffffu, ss, off);
    if ((tid & 31) == 0) red[tid >> 5] = ss;
    __syncthreads();
    if (tid == 0) {
        float s = 0.f;
        #pragma unroll
        for (int i = 0; i < 8; i++) s += red[i];
        s_inv = rsqrtf(s / (float)H_DIM + 1e-6f);
    }
    __syncthreads();
    float inv = s_inv;
    const float4* wp = (const float4*)w;
    float4 wv = wp[tid];
    float4 o;
    o.x = v.x * inv * wv.x; o.y = v.y * inv * wv.y;
    o.z = v.z * inv * wv.z; o.w = v.w * inv * wv.w;
    ((float4*)(y + (size_t)t * H_DIM))[tid] = o;
}

// ---------------- tf32 tensor-core GEMM 128x128x16, 256 thr, mma.m16n8k8 ----------------
// MODE 0: C = A@B            MODE 1: C = Cadd + A@B
// MODE 2: per-expert gather rows of A via asg_tok; C row = e*TCAP + local
// MODE 3: per-expert A row = e*TCAP+local; atomicAdd into C[tok] scaled by asg_w
// DUAL 1: blockIdx.z LSB selects (B,C) vs (B2,C2); remaining bits = expert
template<int MODE, int DUAL>
__global__ __launch_bounds__(256)
void gemm_tc(const float* __restrict__ A, const float* __restrict__ B,
             float* __restrict__ C, const float* __restrict__ Cadd,
             const int* __restrict__ cnts, const int* __restrict__ asg_tok,
             const float* __restrict__ asg_w,
             const float* __restrict__ B2, float* __restrict__ C2,
             int M, int N, int K)
{
    __shared__ uint32_t As[2][16][136];   // K-major: As[k][m]
    __shared__ uint32_t Bs[2][16][136];   // Bs[k][n]
    int e = 0;
    int Mloc = M;
    int zz = blockIdx.z;
    if (DUAL) {
        int sel = zz & 1;
        zz >>= 1;
        if (sel) { B = B2; C = C2; }
    }
    if (MODE >= 2) {
        e = zz;
        Mloc = cnts[e];
        B += (size_t)e * K * N;
    }
    int m0 = blockIdx.y * 128;
    int n0 = blockIdx.x * 128;
    if (m0 >= Mloc) return;

    const int tid = threadIdx.x;
    const int lane = tid & 31;
    const int warp = tid >> 5;
    const int gid = lane >> 2, tig = lane & 3;
    const int wm = (warp >> 2) * 64;
    const int wn = (warp & 3) * 32;

    int a_am[2], a_ak[2];
    const float* a_p[2];
    #pragma unroll
    for (int i = 0; i < 2; i++) {
        int idx = tid + i * 256;
        a_am[i] = idx >> 2;
        a_ak[i] = (idx & 3) << 2;
        int row = m0 + a_am[i];
        a_p[i] = nullptr;
        if (row < Mloc) {
            int g = (MODE == 2) ? asg_tok[e * TCAP + row]
                  : ((MODE == 3) ? (e * TCAP + row) : row);
            a_p[i] = A + (size_t)g * K + a_ak[i];
        }
    }
    int b_bk[2], b_bn[2];
    const float* b_p[2];
    #pragma unroll
    for (int i = 0; i < 2; i++) {
        int idx = tid + i * 256;
        b_bk[i] = idx >> 5;
        b_bn[i] = (idx & 31) << 2;
        b_p[i] = B + (size_t)b_bk[i] * N + n0 + b_bn[i];
    }

    float acc[4][4][4];
    #pragma unroll
    for (int mf = 0; mf < 4; mf++)
        #pragma unroll
        for (int nf = 0; nf < 4; nf++)
            #pragma unroll
            for (int r = 0; r < 4; r++) acc[mf][nf][r] = 0.f;

    float4 fa[2], fb[2];
    #pragma unroll
    for (int i = 0; i < 2; i++) {
        fa[i] = a_p[i] ? *(const float4*)(a_p[i]) : make_float4(0.f, 0.f, 0.f, 0.f);
        fb[i] = *(const float4*)(b_p[i]);
    }

    for (int k0 = 0; k0 < K; k0 += 16) {
        int buf = (k0 >> 4) & 1;
        #pragma unroll
        for (int i = 0; i < 2; i++) {
            As[buf][a_ak[i] + 0][a_am[i]] = f2tf(fa[i].x);
            As[buf][a_ak[i] + 1][a_am[i]] = f2tf(fa[i].y);
            As[buf][a_ak[i] + 2][a_am[i]] = f2tf(fa[i].z);
            As[buf][a_ak[i] + 3][a_am[i]] = f2tf(fa[i].w);
            uint4 bv;
            bv.x = f2tf(fb[i].x); bv.y = f2tf(fb[i].y);
            bv.z = f2tf(fb[i].z); bv.w = f2tf(fb[i].w);
            *(uint4*)&Bs[buf][b_bk[i]][b_bn[i]] = bv;
        }
        __syncthreads();
        if (k0 + 16 < K) {
            #pragma unroll
            for (int i = 0; i < 2; i++) {
                fa[i] = a_p[i] ? *(const float4*)(a_p[i] + k0 + 16)
                               : make_float4(0.f, 0.f, 0.f, 0.f);
                fb[i] = *(const float4*)(b_p[i] + (size_t)(k0 + 16) * N);
            }
        }
        #pragma unroll
        for (int ks = 0; ks < 16; ks += 8) {
            uint32_t af[4][4], bf[4][2];
            #pragma unroll
            for (int mf = 0; mf < 4; mf++) {
                int mb = wm + mf * 16 + gid;
                af[mf][0] = As[buf][ks + tig][mb];
                af[mf][1] = As[buf][ks + tig][mb + 8];
                af[mf][2] = As[buf][ks + tig + 4][mb];
                af[mf][3] = As[buf][ks + tig + 4][mb + 8];
            }
            #pragma unroll
            for (int nf = 0; nf < 4; nf++) {
                int nb = wn + nf * 8 + gid;
                bf[nf][0] = Bs[buf][ks + tig][nb];
                bf[nf][1] = Bs[buf][ks + tig + 4][nb];
            }
            #pragma unroll
            for (int mf = 0; mf < 4; mf++)
                #pragma unroll
                for (int nf = 0; nf < 4; nf++)
                    mma_tf32(acc[mf][nf], af[mf], bf[nf][0], bf[nf][1]);
        }
        __syncthreads();
    }

    #pragma unroll
    for (int mf = 0; mf < 4; mf++) {
        int r0 = m0 + wm + mf * 16 + gid;
        int r1 = r0 + 8;
        #pragma unroll
        for (int nf = 0; nf < 4; nf++) {
            int col = n0 + wn + nf * 8 + tig * 2;
            if (MODE == 3) {
                if (r0 < Mloc) {
                    int tok = asg_tok[e * TCAP + r0];
                    float w = asg_w[e * TCAP + r0];
                    float* cp = C + (size_t)tok * N + col;
                    atomicAdd(cp, w * acc[mf][nf][0]);
                    atomicAdd(cp + 1, w * acc[mf][nf][1]);
                }
                if (r1 < Mloc) {
                    int tok = asg_tok[e * TCAP + r1];
                    float w = asg_w[e * TCAP + r1];
                    float* cp = C + (size_t)tok * N + col;
                    atomicAdd(cp, w * acc[mf][nf][2]);
                    atomicAdd(cp + 1, w * acc[mf][nf][3]);
                }
            } else {
                if (r0 < Mloc) {
                    size_t cr = (MODE == 2) ? (size_t)(e * TCAP + r0) : (size_t)r0;
                    float2 v = make_float2(acc[mf][nf][0], acc[mf][nf][1]);
                    if (MODE == 1) {
                        float2 av = *(const float2*)(Cadd + (size_t)r0 * N + col);
                        v.x += av.x; v.y += av.y;
                    }
                    *(float2*)(C + cr * N + col) = v;
                }
                if (r1 < Mloc) {
                    size_t cr = (MODE == 2) ? (size_t)(e * TCAP + r1) : (size_t)r1;
                    float2 v = make_float2(acc[mf][nf][2], acc[mf][nf][3]);
                    if (MODE == 1) {
                        float2 av = *(const float2*)(Cadd + (size_t)r1 * N + col);
                        v.x += av.x; v.y += av.y;
                    }
                    *(float2*)(C + cr * N + col) = v;
                }
            }
        }
    }
}

// ---------------- RoPE (in-place on g_qkv) ----------------
__global__ void rope_kernel(const int* __restrict__ pos_ids)
{
    int t = blockIdx.x;
    float p = (float)pos_ids[t];
    const float c_l2 = -19.93156856932417f / 32.f;  // -log2(1e6)/32
    float* row = g_qkv + (size_t)t * QKV_N;
    for (int i = threadIdx.x; i < (NH + NKV) * 32; i += blockDim.x) {
        float* base;
        int d;
        if (i < NH * 32) {
            base = row + (size_t)(i >> 5) * HD;          // q heads
            d = i & 31;
        } else {
            int j = i - NH * 32;
            base = row + 1024 + (size_t)(j >> 5) * HD;   // k heads
            d = j & 31;
        }
        float f = p * exp2f((float)d * c_l2);
        float sn, cs;
        sincosf(f, &sn, &cs);
        float a = base[d], b2 = base[d + 32];
        base[d] = a * cs - b2 * sn;
        base[d + 32] = b2 * cs + a * sn;
    }
}

// ---------------- tensor-core flash attention ----------------
// Block: 128 q-rows x 1 head x 1 batch. 8 warps, each owns a 16-row strip.
// QK^T and P*V via mma.m16n8k8 tf32. K/V/P stored in smem pre-converted to tf32.
#define ATR 72                               // smem stride (conflict-free frag patterns)
#define ATT_SMEM ((128 * ATR + 64 * ATR) * 4)
__global__ __launch_bounds__(256)
void attn_tc_kernel()
{
    extern __shared__ uint32_t usm[];
    uint32_t* Qs = usm;                // [128][ATR] tf32 Q, later reused as P
    uint32_t* Ks = usm + 128 * ATR;    // [64][ATR]  tf32 K, then V
    const int qb = gridDim.x - 1 - blockIdx.x;   // heavy blocks first
    const int h = blockIdx.y, b = blockIdx.z;
    const int kvh = h >> 2;
    const int tid = threadIdx.x;
    const int lane = tid & 31, warp = tid >> 5;
    const int gid = lane >> 2, tig = lane & 3;
    const int m0 = warp * 16;

    // stage Q tile (128 x 64) into smem as tf32
    for (int i = tid; i < 128 * 16; i += 256) {
        int row = i >> 4, c4 = (i & 15) << 2;
        float4 v = *(const float4*)(g_qkv + ((size_t)(b * S_LEN + qb * 128 + row)) * QKV_N + h * HD + c4);
        uint4 u;
        u.x = f2tf(v.x); u.y = f2tf(v.y); u.z = f2tf(v.z); u.w = f2tf(v.w);
        *(uint4*)(Qs + row * ATR + c4) = u;
    }
    __syncthreads();
    // Q fragments -> registers (whole block lifetime)
    uint32_t qa[8][4];
    #pragma unroll
    for (int ks = 0; ks < 8; ks++) {
        int k = ks * 8;
        qa[ks][0] = Qs[(m0 + gid) * ATR + k + tig];
        qa[ks][1] = Qs[(m0 + gid + 8) * ATR + k + tig];
        qa[ks][2] = Qs[(m0 + gid) * ATR + k + tig + 4];
        qa[ks][3] = Qs[(m0 + gid + 8) * ATR + k + tig + 4];
    }
    __syncthreads();   // Qs now free -> reused as P strip per warp

    float mr0 = -1e30f, mr1 = -1e30f, l0 = 0.f, l1 = 0.f;
    float oacc[8][4];
    #pragma unroll
    for (int nf = 0; nf < 8; nf++)
        #pragma unroll
        for (int r = 0; r < 4; r++) oacc[nf][r] = 0.f;

    const int qrow0 = qb * 128 + m0 + gid;
    const int qrow1 = qrow0 + 8;
    const int ntile = 2 * qb + 2;

    for (int j = 0; j < ntile; j++) {
        // load K tile (64 kv x 64 d) as tf32
        for (int i = tid; i < 64 * 16; i += 256) {
            int row = i >> 4, c4 = (i & 15) << 2;
            float4 v = *(const float4*)(g_qkv + ((size_t)(b * S_LEN + j * 64 + row)) * QKV_N + 1024 + kvh * HD + c4);
            uint4 u;
            u.x = f2tf(v.x); u.y = f2tf(v.y); u.z = f2tf(v.z); u.w = f2tf(v.w);
            *(uint4*)(Ks + row * ATR + c4) = u;
        }
        __syncthreads();

        // S = Q K^T (m16 x n64 per warp)
        float s[8][4];
        #pragma unroll
        for (int nf = 0; nf < 8; nf++)
            #pragma unroll
            for (int r = 0; r < 4; r++) s[nf][r] = 0.f;
        #pragma unroll
        for (int ks = 0; ks < 8; ks++) {
            #pragma unroll
            for (int nf = 0; nf < 8; nf++) {
                uint32_t b0 = Ks[(nf * 8 + gid) * ATR + ks * 8 + tig];
                uint32_t b1 = Ks[(nf * 8 + gid) * ATR + ks * 8 + tig + 4];
                mma_tf32(s[nf], qa[ks], b0, b1);
            }
        }

        // scale + causal mask (diagonal tiles only)
        bool diag = (j >= 2 * qb);
        #pragma unroll
        for (int nf = 0; nf < 8; nf++) {
            int col = j * 64 + nf * 8 + tig * 2;
            s[nf][0] *= 0.125f; s[nf][1] *= 0.125f;
            s[nf][2] *= 0.125f; s[nf][3] *= 0.125f;
            if (diag) {
                if (col > qrow0)     s[nf][0] = -1e30f;
                if (col + 1 > qrow0) s[nf][1] = -1e30f;
                if (col > qrow1)     s[nf][2] = -1e30f;
                if (col + 1 > qrow1) s[nf][3] = -1e30f;
            }
        }

        // row maxima (rows gid and gid+8), reduce over quad (tig lanes)
        float mx0 = -1e30f, mx1 = -1e30f;
        #pragma unroll
        for (int nf = 0; nf < 8; nf++) {
            mx0 = fmaxf(mx0, fmaxf(s[nf][0], s[nf][1]));
            mx1 = fmaxf(mx1, fmaxf(s[nf][2], s[nf][3]));
        }
        mx0 = fmaxf(mx0, __shfl_xor_sync(0xffffffffu, mx0, 1));
        mx0 = fmaxf(mx0, __shfl_xor_sync(0xffffffffu, mx0, 2));
        mx1 = fmaxf(mx1, __shfl_xor_sync(0xffffffffu, mx1, 1));
        mx1 = fmaxf(mx1, __shfl_xor_sync(0xffffffffu, mx1, 2));
        float mn0 = fmaxf(mr0, mx0), mn1 = fmaxf(mr1, mx1);
        float al0 = __expf(mr0 - mn0), al1 = __expf(mr1 - mn1);
        mr0 = mn0; mr1 = mn1;

        float ls0 = 0.f, ls1 = 0.f;
        #pragma unroll
        for (int nf = 0; nf < 8; nf++) {
            s[nf][0] = __expf(s[nf][0] - mn0);
            s[nf][1] = __expf(s[nf][1] - mn0);
            s[nf][2] = __expf(s[nf][2] - mn1);
            s[nf][3] = __expf(s[nf][3] - mn1);
            ls0 += s[nf][0] + s[nf][1];
            ls1 += s[nf][2] + s[nf][3];
        }
        ls0 += __shfl_xor_sync(0xffffffffu, ls0, 1);
        ls0 += __shfl_xor_sync(0xffffffffu, ls0, 2);
        ls1 += __shfl_xor_sync(0xffffffffu, ls1, 1);
        ls1 += __shfl_xor_sync(0xffffffffu, ls1, 2);
        l0 = l0 * al0 + ls0;
        l1 = l1 * al1 + ls1;
        #pragma unroll
        for (int nf = 0; nf < 8; nf++) {
            oacc[nf][0] *= al0; oacc[nf][1] *= al0;
            oacc[nf][2] *= al1; oacc[nf][3] *= al1;
        }

        // write P (tf32) to warp-private rows of Qs
        #pragma unroll
        for (int nf = 0; nf < 8; nf++) {
            int cl = nf * 8 + tig * 2;
            uint2 p01 = make_uint2(f2tf(s[nf][0]), f2tf(s[nf][1]));
            uint2 p23 = make_uint2(f2tf(s[nf][2]), f2tf(s[nf][3]));
            *(uint2*)(Qs + (m0 + gid) * ATR + cl) = p01;
            *(uint2*)(Qs + (m0 + gid + 8) * ATR + cl) = p23;
        }
        __syncthreads();   // all warps done reading K

        // load V tile (64 kv x 64 d) as tf32 (overwrites Ks)
        for (int i = tid; i < 64 * 16; i += 256) {
            int row = i >> 4, c4 = (i & 15) << 2;
            float4 v = *(const float4*)(g_qkv + ((size_t)(b * S_LEN + j * 64 + row)) * QKV_N + 1280 + kvh * HD + c4);
            uint4 u;
            u.x = f2tf(v.x); u.y = f2tf(v.y); u.z = f2tf(v.z); u.w = f2tf(v.w);
            *(uint4*)(Ks + row * ATR + c4) = u;
        }
        __syncthreads();

        // O += P * V  (A = P m16 x k64 from own strip, B = V[k][n])
        #pragma unroll
        for (int ks = 0; ks < 8; ks++) {
            uint32_t pa[4];
            pa[0] = Qs[(m0 + gid) * ATR + ks * 8 + tig];
            pa[1] = Qs[(m0 + gid + 8) * ATR + ks * 8 + tig];
            pa[2] = Qs[(m0 + gid) * ATR + ks * 8 + tig + 4];
            pa[3] = Qs[(m0 + gid + 8) * ATR + ks * 8 + tig + 4];
            #pragma unroll
            for (int nf = 0; nf < 8; nf++) {
                uint32_t b0 = Ks[(ks * 8 + tig) * ATR + nf * 8 + gid];
                uint32_t b1 = Ks[(ks * 8 + tig + 4) * ATR + nf * 8 + gid];
                mma_tf32(oacc[nf], pa, b0, b1);
            }
        }
        __syncthreads();   // before next tile overwrites Ks
    }

    float inv0 = 1.f / l0, inv1 = 1.f / l1;
    #pragma unroll
    for (int nf = 0; nf < 8; nf++) {
        int col = h * HD + nf * 8 + tig * 2;
        float2 o0 = make_float2(oacc[nf][0] * inv0, oacc[nf][1] * inv0);
        float2 o1 = make_float2(oacc[nf][2] * inv1, oacc[nf][3] * inv1);
        *(float2*)(g_attn + ((size_t)(b * S_LEN + qrow0)) * (NH * HD) + col) = o0;
        *(float2*)(g_attn + ((size_t)(b * S_LEN + qrow1)) * (NH * HD) + col) = o1;
    }
}

// ---------------- router: softmax + top2 + assignment lists ----------------
__global__ void router_kernel(const float* __restrict__ rw)
{
    int warp = threadIdx.x >> 5, lane = threadIdx.x & 31;
    int t = blockIdx.x * 8 + warp;
    const float* xr = g_x2 + (size_t)t * H_DIM;
    float a[8];
    #pragma unroll
    for (int i = 0; i < 8; i++) a[i] = 0.f;
    for (int k = lane; k < H_DIM; k += 32) {
        float xv = xr[k];
        const float4* wp = (const float4*)(rw + (size_t)k * 8);
        float4 w0 = wp[0], w1 = wp[1];
        a[0] += xv * w0.x; a[1] += xv * w0.y; a[2] += xv * w0.z; a[3] += xv * w0.w;
        a[4] += xv * w1.x; a[5] += xv * w1.y; a[6] += xv * w1.z; a[7] += xv * w1.w;
    }
    #pragma unroll
    for (int off = 16; off; off >>= 1)
        #pragma unroll
        for (int i = 0; i < 8; i++) a[i] += __shfl_xor_sync(0xffffffffu, a[i], off);
    if (lane == 0) {
        float mx = a[0];
        #pragma unroll
        for (int i = 1; i < 8; i++) mx = fmaxf(mx, a[i]);
        float p[8], sum = 0.f;
        #pragma unroll
        for (int i = 0; i < 8; i++) { p[i] = expf(a[i] - mx); sum += p[i]; }
        float inv = 1.f / sum;
        #pragma unroll
        for (int i = 0; i < 8; i++) { p[i] *= inv; g_probs[t * 8 + i] = p[i]; }
        int i1 = 0; float v1 = p[0];
        #pragma unroll
        for (int i = 1; i < 8; i++) if (p[i] > v1) { v1 = p[i]; i1 = i; }
        int i2 = -1; float v2 = -1.f;
        #pragma unroll
        for (int i = 0; i < 8; i++) if (i != i1 && p[i] > v2) { v2 = p[i]; i2 = i; }
        int s1 = atomicAdd(&g_cnt[i1], 1);
        g_asg_tok[i1 * TCAP + s1] = t; g_asg_w[i1 * TCAP + s1] = v1;
        int s2 = atomicAdd(&g_cnt[i2], 1);
        g_asg_tok[i2 * TCAP + s2] = t; g_asg_w[i2 * TCAP + s2] = v2;
    }
}

// ---------------- silu(G)*U in place (G), float4 ----------------
__global__ void silumul_kernel(int use_cnt)
{
    int e = blockIdx.y;
    int row = blockIdx.x;
    if (use_cnt && row >= g_cnt[e]) return;
    float4* gp = (float4*)(g_G + ((size_t)e * TCAP + row) * I_DIM);
    const float4* up = (const float4*)(g_U + ((size_t)e * TCAP + row) * I_DIM);
    int i = threadIdx.x;   // 256 threads x 4 = 1024 = I_DIM
    float4 g = gp[i];
    float4 u = up[i];
    g.x = (g.x / (1.f + __expf(-g.x))) * u.x;
    g.y = (g.y / (1.f + __expf(-g.y))) * u.y;
    g.z = (g.z / (1.f + __expf(-g.z))) * u.z;
    g.w = (g.w / (1.f + __expf(-g.w))) * u.w;
    gp[i] = g;
}

// ---------------- shared-expert sigmoid gate ----------------
__global__ void sgate_kernel(const float* __restrict__ segw)
{
    int warp = threadIdx.x >> 5, lane = threadIdx.x & 31;
    int t = blockIdx.x * 8 + warp;
    const float* xr = g_x2 + (size_t)t * H_DIM;
    float a = 0.f;
    for (int k = lane; k < H_DIM; k += 32) a += xr[k] * segw[k];
    #pragma unroll
    for (int off = 16; off; off >>= 1) a += __shfl_xor_sync(0xffffffffu, a, off);
    if (lane == 0) g_sgate[t] = 1.f / (1.f + expf(-a));
}

// ---------------- final combine ----------------
__global__ void combine_kernel(float* __restrict__ out)
{
    int i = blockIdx.x * blockDim.x + threadIdx.x;
    if (i < T_TOK * H_DIM)
        out[i] = g_resid[i] + g_moe[i] + g_sgate[i >> 10] * g_x1[i];
}

// ---------------- aux loss ----------------
__global__ void aux_kernel(float* __restrict__ out_aux)
{
    __shared__ float sm[256];
    int tid = threadIdx.x;
    int e = tid & 7;
    int chunk = tid >> 3;
    float s = 0.f;
    for (int t = chunk; t < T_TOK; t += 32) s += g_probs[t * 8 + e];
    sm[tid] = s;
    __syncthreads();
    for (int st = 16; st >= 1; st >>= 1) {
        if (chunk < st) sm[tid] += sm[tid + st * 8];
        __syncthreads();
    }
    if (tid == 0) {
        float aux = 0.f;
        #pragma unroll
        for (int i = 0; i < 8; i++) {
            float m = sm[i] / (float)T_TOK - 0.125f;
            aux += m * m;
        }
        out_aux[0] = aux / 8.f;
    }
}

// ---------------- launch ----------------
extern "C" void kernel_launch(void* const* d_in, const int* in_sizes, int n_in,
                              void* d_out, int out_size)
{
    const float* hidden = (const float*)d_in[0];
    const int*   pos    = (const int*)d_in[2];
    const float* ln1    = (const float*)d_in[3];
    const float* ln2    = (const float*)d_in[4];
    const float* wq     = (const float*)d_in[5];
    const float* wk     = (const float*)d_in[6];
    const float* wv     = (const float*)d_in[7];
    const float* wo     = (const float*)d_in[8];
    const float* rw     = (const float*)d_in[9];
    const float* egw    = (const float*)d_in[10];
    const float* euw    = (const float*)d_in[11];
    const float* edw    = (const float*)d_in[12];
    const float* sgw    = (const float*)d_in[13];
    const float* suw    = (const float*)d_in[14];
    const float* sdw    = (const float*)d_in[15];
    const float* segw   = (const float*)d_in[16];
    float* out = (float*)d_out;

    float *x1, *qkv, *attn, *resid, *x2, *moe, *G, *U, *asw, *wqkv;
    int *cnt, *ast;
    cudaGetSymbolAddress((void**)&x1, g_x1);
    cudaGetSymbolAddress((void**)&qkv, g_qkv);
    cudaGetSymbolAddress((void**)&attn, g_attn);
    cudaGetSymbolAddress((void**)&resid, g_resid);
    cudaGetSymbolAddress((void**)&x2, g_x2);
    cudaGetSymbolAddress((void**)&moe, g_moe);
    cudaGetSymbolAddress((void**)&G, g_G);
    cudaGetSymbolAddress((void**)&U, g_U);
    cudaGetSymbolAddress((void**)&cnt, g_cnt);
    cudaGetSymbolAddress((void**)&ast, g_asg_tok);
    cudaGetSymbolAddress((void**)&asw, g_asg_w);
    cudaGetSymbolAddress((void**)&wqkv, g_wqkv);

    cudaFuncSetAttribute((const void*)attn_tc_kernel,
                         cudaFuncAttributeMaxDynamicSharedMemorySize, ATT_SMEM);

    zero_kernel<<<(T_TOK * H_DIM + 255) / 256, 256>>>();
    concat_qkv_w<<<(H_DIM * QKV_N + 255) / 256, 256>>>(wq, wk, wv);

    // attention block
    rmsnorm_kernel<<<T_TOK, 256>>>(hidden, ln1, x1);
    gemm_tc<0, 0><<<dim3(12, 16), 256>>>(x1, wqkv, qkv, nullptr, nullptr, nullptr, nullptr, nullptr, nullptr, T_TOK, QKV_N, 1024);
    rope_kernel<<<T_TOK, 256>>>(pos);
    attn_tc_kernel<<<dim3(8, NH, B_SZ), 256, ATT_SMEM>>>();
    gemm_tc<1, 0><<<dim3(8, 16), 256>>>(attn, wo, resid, hidden, nullptr, nullptr, nullptr, nullptr, nullptr, T_TOK, 1024, 1024);

    // MoE block
    rmsnorm_kernel<<<T_TOK, 256>>>(resid, ln2, x2);
    router_kernel<<<T_TOK / 8, 256>>>(rw);
    gemm_tc<2, 1><<<dim3(8, 16, NE * 2), 256>>>(x2, egw, G, nullptr, cnt, ast, nullptr, euw, U, TCAP, 1024, 1024);
    silumul_kernel<<<dim3(TCAP, NE), 256>>>(1);
    gemm_tc<3, 0><<<dim3(8, 16, NE), 256>>>(G, edw, moe, nullptr, cnt, ast, asw, nullptr, nullptr, TCAP, 1024, 1024);

    // shared expert
    gemm_tc<0, 1><<<dim3(8, 16, 2), 256>>>(x2, sgw, G, nullptr, nullptr, nullptr, nullptr, suw, U, T_TOK, 1024, 1024);
    silumul_kernel<<<dim3(T_TOK, 1), 256>>>(0);
    gemm_tc<0, 0><<<dim3(8, 16), 256>>>(G, sdw, x1, nullptr, nullptr, nullptr, nullptr, nullptr, nullptr, T_TOK, 1024, 1024);
    sgate_kernel<<<T_TOK / 8, 256>>>(segw);

    combine_kernel<<<(T_TOK * H_DIM + 255) / 256, 256>>>(out);
    if (out_size > T_TOK * H_DIM)
        aux_kernel<<<1, 256>>>(out + (out_size - 1));
}